// round 2
// baseline (speedup 1.0000x reference)
#include <cuda_runtime.h>
#include <math.h>

#define BB 2
#define LL 1024
#define DM 768
#define DI 1536
#define DS 16
#define DTR 48
#define XD 80              // DT_RANK + 2*D_STATE
#define MTOK (BB*LL)       // 2048 tokens

// ---------------- scratch (device globals; no allocation allowed) ----------------
__device__ __align__(128) float g_xz   [(size_t)BB*LL*2*DI];   // in_proj output, orig order
__device__ __align__(128) float g_xt   [(size_t)2*BB*LL*DI];   // conv+silu out, per-dir order
__device__ __align__(128) float g_xdbl [(size_t)2*BB*LL*XD];   // x_proj out, per-dir order
__device__ __align__(128) float g_delta[(size_t)2*BB*LL*DI];   // softplus(dt proj), per-dir order
__device__ __align__(128) float g_y    [(size_t)2*BB*LL*DI];   // gated scan out, ORIG order per dir

__device__ __forceinline__ float softplusf(float x) {
    return fmaxf(x, 0.f) + log1pf(expf(-fabsf(x)));
}

// ---------------- generic fp32 TN GEMM: C[m,n] = act(sum_k A[m,k]*W[n,k] + bias[n]) ----
// A may be the elementwise sum of two tensors (A2 != nullptr) — used to fuse y_f + y_r.
// BM=BN=128, BK=16, 256 threads, 8x8 per thread.
__global__ void __launch_bounds__(256) sgemm_tn(
    const float* __restrict__ A, const float* __restrict__ A2,
    const float* __restrict__ W, const float* __restrict__ bias,
    float* __restrict__ C, int M, int N, int K, int lda, int act)
{
    __shared__ float As[16][128];
    __shared__ float Ws[16][128];
    const int m0 = blockIdx.y * 128;
    const int n0 = blockIdx.x * 128;
    const int t  = threadIdx.x;
    const int tx = t & 15, ty = t >> 4;

    float acc[8][8];
    #pragma unroll
    for (int i = 0; i < 8; i++)
        #pragma unroll
        for (int j = 0; j < 8; j++) acc[i][j] = 0.f;

    for (int k0 = 0; k0 < K; k0 += 16) {
        #pragma unroll
        for (int it = 0; it < 2; it++) {
            int idx = t + it * 256;
            int row = idx >> 2;
            int kq  = (idx & 3) << 2;
            float4 v = *(const float4*)(A + (size_t)(m0 + row) * lda + k0 + kq);
            if (A2) {
                float4 v2 = *(const float4*)(A2 + (size_t)(m0 + row) * lda + k0 + kq);
                v.x += v2.x; v.y += v2.y; v.z += v2.z; v.w += v2.w;
            }
            As[kq+0][row] = v.x; As[kq+1][row] = v.y;
            As[kq+2][row] = v.z; As[kq+3][row] = v.w;

            float4 w = make_float4(0.f, 0.f, 0.f, 0.f);
            if (n0 + row < N)
                w = *(const float4*)(W + (size_t)(n0 + row) * K + k0 + kq);
            Ws[kq+0][row] = w.x; Ws[kq+1][row] = w.y;
            Ws[kq+2][row] = w.z; Ws[kq+3][row] = w.w;
        }
        __syncthreads();

        #pragma unroll
        for (int k = 0; k < 16; k++) {
            float a[8], b[8];
            *(float4*)&a[0] = *(const float4*)&As[k][ty * 4];
            *(float4*)&a[4] = *(const float4*)&As[k][64 + ty * 4];
            *(float4*)&b[0] = *(const float4*)&Ws[k][tx * 4];
            *(float4*)&b[4] = *(const float4*)&Ws[k][64 + tx * 4];
            #pragma unroll
            for (int i = 0; i < 8; i++)
                #pragma unroll
                for (int j = 0; j < 8; j++)
                    acc[i][j] = fmaf(a[i], b[j], acc[i][j]);
        }
        __syncthreads();
    }

    #pragma unroll
    for (int i = 0; i < 8; i++) {
        int m = m0 + ((i < 4) ? (ty * 4 + i) : (64 + ty * 4 + i - 4));
        #pragma unroll
        for (int j = 0; j < 8; j++) {
            int n = n0 + ((j < 4) ? (tx * 4 + j) : (64 + tx * 4 + j - 4));
            if (n < N) {
                float v = acc[i][j];
                if (bias) v += bias[n];
                if (act == 1) v = softplusf(v);
                C[(size_t)m * N + n] = v;
            }
        }
    }
}

// ---------------- depthwise causal conv1d + silu, both directions ----------------
// Reads x-half of xz (orig order, flipped gather for reverse dir),
// writes xt in direction-local order [dir][b][p][d].
__global__ void conv_silu_kernel(
    const float* __restrict__ xz,
    const float* __restrict__ cwf, const float* __restrict__ cbf,
    const float* __restrict__ cwr, const float* __restrict__ cbr,
    float* __restrict__ xt)
{
    long idx = (long)blockIdx.x * blockDim.x + threadIdx.x;
    if (idx >= (long)2 * BB * LL * DI) return;
    int d   = (int)(idx % DI);
    int p   = (int)((idx / DI) % LL);
    int b   = (int)((idx / ((long)DI * LL)) % BB);
    int dir = (int)(idx / ((long)DI * LL * BB));

    const float* cw = dir ? cwr : cwf;
    const float* cb = dir ? cbr : cbf;
    float4 w4 = *(const float4*)(cw + d * 4);
    float wv[4] = {w4.x, w4.y, w4.z, w4.w};

    float acc = cb[d];
    const float* xbase = xz + (size_t)b * LL * 2 * DI + d;
    #pragma unroll
    for (int j = 0; j < 4; j++) {
        int q = p - 3 + j;
        if (q >= 0) {
            int ol = dir ? (LL - 1 - q) : q;
            acc = fmaf(wv[j], xbase[(size_t)ol * 2 * DI], acc);
        }
    }
    float s = acc / (1.f + __expf(-acc));   // silu
    xt[idx] = s;
}

// ---------------- skinny-N GEMM for x_proj: (2048 x 1536) @ (1536 x 80) per dir ----
// BM=16 rows x all 80 cols per block; grid (128, 2 dirs). Avoids the 16-block
// underutilization a 128x128 tiling would give at N=80.
__global__ void __launch_bounds__(256) xproj_gemm(
    const float* __restrict__ xt,
    const float* __restrict__ wf, const float* __restrict__ wr,
    float* __restrict__ xdbl)
{
    int dir = blockIdx.y;
    const float* W = dir ? wr : wf;
    const float* A = xt   + (size_t)dir * BB * LL * DI;
    float*       C = xdbl + (size_t)dir * BB * LL * XD;
    int m0 = blockIdx.x * 16;

    __shared__ float As[32][16];
    __shared__ float Ws[32][XD];
    int t  = threadIdx.x;
    int m  = t >> 4;          // 0..15
    int nb = (t & 15) * 5;    // 0,5,...,75

    float acc[5] = {0.f, 0.f, 0.f, 0.f, 0.f};
    for (int k0 = 0; k0 < DI; k0 += 32) {
        #pragma unroll
        for (int it = 0; it < 2; it++) {      // 16*32 = 512 floats
            int idx = t + it * 256;
            int row = idx >> 5, kk = idx & 31;
            As[kk][row] = A[(size_t)(m0 + row) * DI + k0 + kk];
        }
        #pragma unroll
        for (int it = 0; it < 10; it++) {     // 80*32 = 2560 floats
            int idx = t + it * 256;
            int row = idx >> 5, kk = idx & 31;
            Ws[kk][row] = W[(size_t)row * DI + k0 + kk];
        }
        __syncthreads();
        #pragma unroll
        for (int k = 0; k < 32; k++) {
            float a = As[k][m];
            #pragma unroll
            for (int j = 0; j < 5; j++)
                acc[j] = fmaf(a, Ws[k][nb + j], acc[j]);
        }
        __syncthreads();
    }
    #pragma unroll
    for (int j = 0; j < 5; j++)
        C[(size_t)(m0 + m) * XD + nb + j] = acc[j];
}

// ---------------- selective scan, both directions, fused D-skip + silu(z) gate ----
// 2 channels per warp: lanes 0-15 -> channel d0 (state n = lane), lanes 16-31 -> d1.
// Writes y at ORIGINAL sequence position (flip applied for reverse dir), so the
// final out_proj just sums the two direction buffers.
__global__ void __launch_bounds__(128) scan_kernel(
    const float* __restrict__ xz,   const float* __restrict__ xt,
    const float* __restrict__ xdbl, const float* __restrict__ delta,
    const float* __restrict__ Alog_f, const float* __restrict__ Df,
    const float* __restrict__ Alog_r, const float* __restrict__ Dr,
    float* __restrict__ y)
{
    int dir  = blockIdx.z, b = blockIdx.y;
    int warp = threadIdx.x >> 5, lane = threadIdx.x & 31;
    int half = (lane >> 4) & 1, n = lane & 15;
    int d = blockIdx.x * 8 + warp * 2 + half;

    const float* Alog = dir ? Alog_r : Alog_f;
    const float* Dp   = dir ? Dr     : Df;
    float Acoef = -expf(Alog[d * DS + n]);
    float Dd    = Dp[d];

    const float* pdl = delta + ((size_t)(dir * BB + b) * LL) * DI + d;
    const float* pu  = xt    + ((size_t)(dir * BB + b) * LL) * DI + d;
    const float* px  = xdbl  + ((size_t)(dir * BB + b) * LL) * XD;
    const float* pz  = xz    + (size_t)b * LL * 2 * DI + DI + d;
    float*       py  = y     + ((size_t)(dir * BB + b) * LL) * DI + d;

    float h = 0.f;
    #pragma unroll 4
    for (int t = 0; t < LL; t++) {
        float dt_ = pdl[(size_t)t * DI];
        float u   = pu [(size_t)t * DI];
        float Bv  = px[t * XD + DTR + n];
        float Cv  = px[t * XD + DTR + DS + n];
        float dA  = __expf(dt_ * Acoef);
        h = fmaf(dA, h, (dt_ * u) * Bv);
        float part = h * Cv;
        part += __shfl_down_sync(0xffffffffu, part, 8, 16);
        part += __shfl_down_sync(0xffffffffu, part, 4, 16);
        part += __shfl_down_sync(0xffffffffu, part, 2, 16);
        part += __shfl_down_sync(0xffffffffu, part, 1, 16);
        if (n == 0) {
            int ol = dir ? (LL - 1 - t) : t;
            float zv = pz[(size_t)ol * 2 * DI];
            float yv = part + Dd * u;
            float sg = zv / (1.f + __expf(-zv));   // silu(z)
            py[(size_t)ol * DI] = yv * sg;
        }
    }
}

// ---------------- launch ----------------
extern "C" void kernel_launch(void* const* d_in, const int* in_sizes, int n_in,
                              void* d_out, int out_size)
{
    const float* hs   = (const float*)d_in[0];   // hidden_states (2,1024,768)
    const float* wi   = (const float*)d_in[1];   // in_proj_w (3072,768)
    const float* wo   = (const float*)d_in[2];   // out_proj_w (768,1536)
    const float* cwf  = (const float*)d_in[3];
    const float* cbf  = (const float*)d_in[4];
    const float* xpf  = (const float*)d_in[5];
    const float* dtwf = (const float*)d_in[6];
    const float* dtbf = (const float*)d_in[7];
    const float* alf  = (const float*)d_in[8];
    const float* Dfp  = (const float*)d_in[9];
    const float* cwr  = (const float*)d_in[10];
    const float* cbr  = (const float*)d_in[11];
    const float* xpr  = (const float*)d_in[12];
    const float* dtwr = (const float*)d_in[13];
    const float* dtbr = (const float*)d_in[14];
    const float* alr  = (const float*)d_in[15];
    const float* Drp  = (const float*)d_in[16];
    float* out = (float*)d_out;

    float *xz, *xt, *xdbl, *delta, *y;
    cudaGetSymbolAddress((void**)&xz,    g_xz);
    cudaGetSymbolAddress((void**)&xt,    g_xt);
    cudaGetSymbolAddress((void**)&xdbl,  g_xdbl);
    cudaGetSymbolAddress((void**)&delta, g_delta);
    cudaGetSymbolAddress((void**)&y,     g_y);

    const size_t dir_xd  = (size_t)BB * LL * XD;   // per-dir x_dbl stride
    const size_t dir_di  = (size_t)BB * LL * DI;   // per-dir (L,DI) stride

    // 1. shared in_proj (once for both directions): xz = hs @ wi^T
    sgemm_tn<<<dim3(2 * DI / 128, MTOK / 128), 256>>>(
        hs, nullptr, wi, nullptr, xz, MTOK, 2 * DI, DM, DM, 0);

    // 2. depthwise conv + silu, both dirs
    long total = (long)2 * BB * LL * DI;
    conv_silu_kernel<<<(unsigned)((total + 255) / 256), 256>>>(
        xz, cwf, cbf, cwr, cbr, xt);

    // 3. x_proj, both dirs
    xproj_gemm<<<dim3(MTOK / 16, 2), 256>>>(xt, xpf, xpr, xdbl);

    // 4. dt projection + softplus, per dir (A = x_dbl[:, :48], lda = 80)
    sgemm_tn<<<dim3(DI / 128, MTOK / 128), 256>>>(
        xdbl, nullptr, dtwf, dtbf, delta, MTOK, DI, DTR, XD, 1);
    sgemm_tn<<<dim3(DI / 128, MTOK / 128), 256>>>(
        xdbl + dir_xd, nullptr, dtwr, dtbr, delta + dir_di, MTOK, DI, DTR, XD, 1);

    // 5. selective scan + D-skip + silu(z) gate, both dirs (writes orig order)
    scan_kernel<<<dim3(DI / 8, BB, 2), 128>>>(
        xz, xt, xdbl, delta, alf, Dfp, alr, Drp, y);

    // 6. shared out_proj on (y_f + y_r), once
    sgemm_tn<<<dim3(DM / 128, MTOK / 128), 256>>>(
        y, y + dir_di, wo, nullptr, out, MTOK, DM, DI, DI, 0);
}

// round 3
// speedup vs baseline: 1.2651x; 1.2651x over previous
#include <cuda_runtime.h>
#include <math.h>

#define BB 2
#define LL 1024
#define DM 768
#define DI 1536
#define DS 16
#define DTR 48
#define XD 80              // DT_RANK + 2*D_STATE
#define MTOK (BB*LL)       // 2048 tokens

// ---------------- scratch (device globals; no allocation allowed) ----------------
__device__ __align__(128) float g_xz   [(size_t)BB*LL*2*DI];   // in_proj output, orig order
__device__ __align__(128) float g_xt   [(size_t)2*BB*LL*DI];   // conv+silu out, per-dir order
__device__ __align__(128) float g_xdbl [(size_t)2*BB*LL*XD];   // x_proj out, per-dir order
__device__ __align__(128) float g_delta[(size_t)2*BB*LL*DI];   // softplus(dt proj), per-dir order
__device__ __align__(128) float g_y    [(size_t)2*BB*LL*DI];   // gated scan out, ORIG order per dir

__device__ __forceinline__ float softplusf(float x) {
    return fmaxf(x, 0.f) + log1pf(expf(-fabsf(x)));
}

__device__ __forceinline__ unsigned f2tf(float x) {
    unsigned u;
    asm("cvt.rna.tf32.f32 %0, %1;" : "=r"(u) : "f"(x));
    return u;
}

// XOR swizzle: conflict-free for both the float4-k store phase and all
// mma fragment load phases (verified bank math for 32 banks, 4B words).
__device__ __forceinline__ int SW(int k, int m) {
    return m ^ ((((k & 3) ^ (k >> 2)) & 3) << 3);
}

// ---------------- tf32 tensor-core TN GEMM ----------------
// C[m,n] = act(sum_k A[m,k]*W[n,k] + bias[n]); A may be sum of two tensors.
// BM=BN=128, BK=16, 256 threads (8 warps, 2x4), warp tile 64x32 via m16n8k8.
// Requires M%128==0, N%128==0, K%16==0 (all call sites satisfy this).
__global__ void __launch_bounds__(256) tf32_gemm(
    const float* __restrict__ A, const float* __restrict__ A2,
    const float* __restrict__ W, const float* __restrict__ bias,
    float* __restrict__ C, int M, int N, int K, int lda, int act)
{
    __shared__ unsigned As[16][128];
    __shared__ unsigned Ws[16][128];
    const int m0 = blockIdx.y * 128;
    const int n0 = blockIdx.x * 128;
    const int t    = threadIdx.x;
    const int lane = t & 31;
    const int wid  = t >> 5;
    const int wm   = wid & 1;        // 0..1  (M dim, 64 rows each)
    const int wn   = wid >> 1;       // 0..3  (N dim, 32 cols each)
    const int g    = lane >> 2;      // 0..7
    const int tg   = lane & 3;       // 0..3

    // loader mapping: idx = t + it*256, row = idx>>2 (0..127), kq = (idx&3)*4
    const int lrow = t >> 2;         // rows 0..63 (it=0) / +64 (it=1)
    const int lkq  = (t & 3) << 2;

    float acc[4][4][4];
    #pragma unroll
    for (int mt = 0; mt < 4; mt++)
        #pragma unroll
        for (int nt = 0; nt < 4; nt++)
            #pragma unroll
            for (int r = 0; r < 4; r++) acc[mt][nt][r] = 0.f;

    float4 ra[2], rw[2];
    // prefetch k0 = 0
    #pragma unroll
    for (int it = 0; it < 2; it++) {
        int row = lrow + it * 64;
        float4 v = *(const float4*)(A + (size_t)(m0 + row) * lda + lkq);
        if (A2) {
            float4 v2 = *(const float4*)(A2 + (size_t)(m0 + row) * lda + lkq);
            v.x += v2.x; v.y += v2.y; v.z += v2.z; v.w += v2.w;
        }
        ra[it] = v;
        rw[it] = *(const float4*)(W + (size_t)(n0 + row) * K + lkq);
    }

    for (int k0 = 0; k0 < K; k0 += 16) {
        // store prefetched tile to smem (tf32-rounded)
        #pragma unroll
        for (int it = 0; it < 2; it++) {
            int row = lrow + it * 64;
            float av[4] = {ra[it].x, ra[it].y, ra[it].z, ra[it].w};
            float wv[4] = {rw[it].x, rw[it].y, rw[it].z, rw[it].w};
            #pragma unroll
            for (int i = 0; i < 4; i++) {
                As[lkq + i][SW(lkq + i, row)] = f2tf(av[i]);
                Ws[lkq + i][SW(lkq + i, row)] = f2tf(wv[i]);
            }
        }
        __syncthreads();

        // prefetch next tile
        if (k0 + 16 < K) {
            #pragma unroll
            for (int it = 0; it < 2; it++) {
                int row = lrow + it * 64;
                float4 v = *(const float4*)(A + (size_t)(m0 + row) * lda + k0 + 16 + lkq);
                if (A2) {
                    float4 v2 = *(const float4*)(A2 + (size_t)(m0 + row) * lda + k0 + 16 + lkq);
                    v.x += v2.x; v.y += v2.y; v.z += v2.z; v.w += v2.w;
                }
                ra[it] = v;
                rw[it] = *(const float4*)(W + (size_t)(n0 + row) * K + k0 + 16 + lkq);
            }
        }

        // compute: two k8 steps
        #pragma unroll
        for (int ks = 0; ks < 16; ks += 8) {
            unsigned a[4][4], b[4][2];
            #pragma unroll
            for (int mt = 0; mt < 4; mt++) {
                int mr = wm * 64 + mt * 16 + g;
                a[mt][0] = As[ks + tg    ][SW(ks + tg,     mr)];
                a[mt][1] = As[ks + tg    ][SW(ks + tg,     mr + 8)];
                a[mt][2] = As[ks + tg + 4][SW(ks + tg + 4, mr)];
                a[mt][3] = As[ks + tg + 4][SW(ks + tg + 4, mr + 8)];
            }
            #pragma unroll
            for (int nt = 0; nt < 4; nt++) {
                int nc = wn * 32 + nt * 8 + g;
                b[nt][0] = Ws[ks + tg    ][SW(ks + tg,     nc)];
                b[nt][1] = Ws[ks + tg + 4][SW(ks + tg + 4, nc)];
            }
            #pragma unroll
            for (int mt = 0; mt < 4; mt++)
                #pragma unroll
                for (int nt = 0; nt < 4; nt++) {
                    asm volatile(
                        "mma.sync.aligned.m16n8k8.row.col.f32.tf32.tf32.f32 "
                        "{%0,%1,%2,%3}, {%4,%5,%6,%7}, {%8,%9}, {%0,%1,%2,%3};"
                        : "+f"(acc[mt][nt][0]), "+f"(acc[mt][nt][1]),
                          "+f"(acc[mt][nt][2]), "+f"(acc[mt][nt][3])
                        : "r"(a[mt][0]), "r"(a[mt][1]), "r"(a[mt][2]), "r"(a[mt][3]),
                          "r"(b[nt][0]), "r"(b[nt][1]));
                }
        }
        __syncthreads();
    }

    // epilogue: c0/c1 at (row g, cols 2tg,2tg+1); c2/c3 at row g+8
    #pragma unroll
    for (int mt = 0; mt < 4; mt++) {
        int r0 = m0 + wm * 64 + mt * 16 + g;
        #pragma unroll
        for (int nt = 0; nt < 4; nt++) {
            int c0 = n0 + wn * 32 + nt * 8 + 2 * tg;
            float v0 = acc[mt][nt][0], v1 = acc[mt][nt][1];
            float v2 = acc[mt][nt][2], v3 = acc[mt][nt][3];
            if (bias) {
                float b0 = bias[c0], b1 = bias[c0 + 1];
                v0 += b0; v1 += b1; v2 += b0; v3 += b1;
            }
            if (act == 1) {
                v0 = softplusf(v0); v1 = softplusf(v1);
                v2 = softplusf(v2); v3 = softplusf(v3);
            }
            *(float2*)(C + (size_t)r0 * N + c0)       = make_float2(v0, v1);
            *(float2*)(C + (size_t)(r0 + 8) * N + c0) = make_float2(v2, v3);
        }
    }
}

// ---------------- depthwise causal conv1d + silu, both directions ----------------
__global__ void conv_silu_kernel(
    const float* __restrict__ xz,
    const float* __restrict__ cwf, const float* __restrict__ cbf,
    const float* __restrict__ cwr, const float* __restrict__ cbr,
    float* __restrict__ xt)
{
    long idx = (long)blockIdx.x * blockDim.x + threadIdx.x;
    if (idx >= (long)2 * BB * LL * DI) return;
    int d   = (int)(idx % DI);
    int p   = (int)((idx / DI) % LL);
    int b   = (int)((idx / ((long)DI * LL)) % BB);
    int dir = (int)(idx / ((long)DI * LL * BB));

    const float* cw = dir ? cwr : cwf;
    const float* cb = dir ? cbr : cbf;
    float4 w4 = *(const float4*)(cw + d * 4);
    float wv[4] = {w4.x, w4.y, w4.z, w4.w};

    float acc = cb[d];
    const float* xbase = xz + (size_t)b * LL * 2 * DI + d;
    #pragma unroll
    for (int j = 0; j < 4; j++) {
        int q = p - 3 + j;
        if (q >= 0) {
            int ol = dir ? (LL - 1 - q) : q;
            acc = fmaf(wv[j], xbase[(size_t)ol * 2 * DI], acc);
        }
    }
    float s = acc / (1.f + __expf(-acc));   // silu
    xt[idx] = s;
}

// ---------------- skinny-N GEMM for x_proj: (2048 x 1536) @ (1536 x 80) per dir ----
__global__ void __launch_bounds__(256) xproj_gemm(
    const float* __restrict__ xt,
    const float* __restrict__ wf, const float* __restrict__ wr,
    float* __restrict__ xdbl)
{
    int dir = blockIdx.y;
    const float* W = dir ? wr : wf;
    const float* A = xt   + (size_t)dir * BB * LL * DI;
    float*       C = xdbl + (size_t)dir * BB * LL * XD;
    int m0 = blockIdx.x * 16;

    __shared__ float As[32][16];
    __shared__ float Ws[32][XD];
    int t  = threadIdx.x;
    int m  = t >> 4;          // 0..15
    int nb = (t & 15) * 5;    // 0,5,...,75

    float acc[5] = {0.f, 0.f, 0.f, 0.f, 0.f};
    for (int k0 = 0; k0 < DI; k0 += 32) {
        #pragma unroll
        for (int it = 0; it < 2; it++) {      // 16*32 = 512 floats
            int idx = t + it * 256;
            int row = idx >> 5, kk = idx & 31;
            As[kk][row] = A[(size_t)(m0 + row) * DI + k0 + kk];
        }
        #pragma unroll
        for (int it = 0; it < 10; it++) {     // 80*32 = 2560 floats
            int idx = t + it * 256;
            int row = idx >> 5, kk = idx & 31;
            Ws[kk][row] = W[(size_t)row * DI + k0 + kk];
        }
        __syncthreads();
        #pragma unroll
        for (int k = 0; k < 32; k++) {
            float a = As[k][m];
            #pragma unroll
            for (int j = 0; j < 5; j++)
                acc[j] = fmaf(a, Ws[k][nb + j], acc[j]);
        }
        __syncthreads();
    }
    #pragma unroll
    for (int j = 0; j < 5; j++)
        C[(size_t)(m0 + m) * XD + nb + j] = acc[j];
}

// ---------------- selective scan, both directions, fused D-skip + silu(z) gate ----
__global__ void __launch_bounds__(128) scan_kernel(
    const float* __restrict__ xz,   const float* __restrict__ xt,
    const float* __restrict__ xdbl, const float* __restrict__ delta,
    const float* __restrict__ Alog_f, const float* __restrict__ Df,
    const float* __restrict__ Alog_r, const float* __restrict__ Dr,
    float* __restrict__ y)
{
    int dir  = blockIdx.z, b = blockIdx.y;
    int warp = threadIdx.x >> 5, lane = threadIdx.x & 31;
    int half = (lane >> 4) & 1, n = lane & 15;
    int d = blockIdx.x * 8 + warp * 2 + half;

    const float* Alog = dir ? Alog_r : Alog_f;
    const float* Dp   = dir ? Dr     : Df;
    float Acoef = -expf(Alog[d * DS + n]);
    float Dd    = Dp[d];

    const float* pdl = delta + ((size_t)(dir * BB + b) * LL) * DI + d;
    const float* pu  = xt    + ((size_t)(dir * BB + b) * LL) * DI + d;
    const float* px  = xdbl  + ((size_t)(dir * BB + b) * LL) * XD;
    const float* pz  = xz    + (size_t)b * LL * 2 * DI + DI + d;
    float*       py  = y     + ((size_t)(dir * BB + b) * LL) * DI + d;

    float h = 0.f;
    #pragma unroll 4
    for (int t = 0; t < LL; t++) {
        float dt_ = pdl[(size_t)t * DI];
        float u   = pu [(size_t)t * DI];
        float Bv  = px[t * XD + DTR + n];
        float Cv  = px[t * XD + DTR + DS + n];
        float dA  = __expf(dt_ * Acoef);
        h = fmaf(dA, h, (dt_ * u) * Bv);
        float part = h * Cv;
        part += __shfl_down_sync(0xffffffffu, part, 8, 16);
        part += __shfl_down_sync(0xffffffffu, part, 4, 16);
        part += __shfl_down_sync(0xffffffffu, part, 2, 16);
        part += __shfl_down_sync(0xffffffffu, part, 1, 16);
        if (n == 0) {
            int ol = dir ? (LL - 1 - t) : t;
            float zv = pz[(size_t)ol * 2 * DI];
            float yv = part + Dd * u;
            float sg = zv / (1.f + __expf(-zv));   // silu(z)
            py[(size_t)ol * DI] = yv * sg;
        }
    }
}

// ---------------- launch ----------------
extern "C" void kernel_launch(void* const* d_in, const int* in_sizes, int n_in,
                              void* d_out, int out_size)
{
    const float* hs   = (const float*)d_in[0];   // hidden_states (2,1024,768)
    const float* wi   = (const float*)d_in[1];   // in_proj_w (3072,768)
    const float* wo   = (const float*)d_in[2];   // out_proj_w (768,1536)
    const float* cwf  = (const float*)d_in[3];
    const float* cbf  = (const float*)d_in[4];
    const float* xpf  = (const float*)d_in[5];
    const float* dtwf = (const float*)d_in[6];
    const float* dtbf = (const float*)d_in[7];
    const float* alf  = (const float*)d_in[8];
    const float* Dfp  = (const float*)d_in[9];
    const float* cwr  = (const float*)d_in[10];
    const float* cbr  = (const float*)d_in[11];
    const float* xpr  = (const float*)d_in[12];
    const float* dtwr = (const float*)d_in[13];
    const float* dtbr = (const float*)d_in[14];
    const float* alr  = (const float*)d_in[15];
    const float* Drp  = (const float*)d_in[16];
    float* out = (float*)d_out;

    float *xz, *xt, *xdbl, *delta, *y;
    cudaGetSymbolAddress((void**)&xz,    g_xz);
    cudaGetSymbolAddress((void**)&xt,    g_xt);
    cudaGetSymbolAddress((void**)&xdbl,  g_xdbl);
    cudaGetSymbolAddress((void**)&delta, g_delta);
    cudaGetSymbolAddress((void**)&y,     g_y);

    const size_t dir_xd  = (size_t)BB * LL * XD;   // per-dir x_dbl stride
    const size_t dir_di  = (size_t)BB * LL * DI;   // per-dir (L,DI) stride

    // 1. shared in_proj (once for both directions): xz = hs @ wi^T
    tf32_gemm<<<dim3(2 * DI / 128, MTOK / 128), 256>>>(
        hs, nullptr, wi, nullptr, xz, MTOK, 2 * DI, DM, DM, 0);

    // 2. depthwise conv + silu, both dirs
    long total = (long)2 * BB * LL * DI;
    conv_silu_kernel<<<(unsigned)((total + 255) / 256), 256>>>(
        xz, cwf, cbf, cwr, cbr, xt);

    // 3. x_proj, both dirs
    xproj_gemm<<<dim3(MTOK / 16, 2), 256>>>(xt, xpf, xpr, xdbl);

    // 4. dt projection + softplus, per dir (A = x_dbl[:, :48], lda = 80)
    tf32_gemm<<<dim3(DI / 128, MTOK / 128), 256>>>(
        xdbl, nullptr, dtwf, dtbf, delta, MTOK, DI, DTR, XD, 1);
    tf32_gemm<<<dim3(DI / 128, MTOK / 128), 256>>>(
        xdbl + dir_xd, nullptr, dtwr, dtbr, delta + dir_di, MTOK, DI, DTR, XD, 1);

    // 5. selective scan + D-skip + silu(z) gate, both dirs (writes orig order)
    scan_kernel<<<dim3(DI / 8, BB, 2), 128>>>(
        xz, xt, xdbl, delta, alf, Dfp, alr, Drp, y);

    // 6. shared out_proj on (y_f + y_r), once
    tf32_gemm<<<dim3(DM / 128, MTOK / 128), 256>>>(
        y, y + dir_di, wo, nullptr, out, MTOK, DM, DI, DI, 0);
}

// round 4
// speedup vs baseline: 1.3938x; 1.1017x over previous
#include <cuda_runtime.h>
#include <math.h>

#define BB 2
#define LL 1024
#define DM 768
#define DI 1536
#define DS 16
#define DTR 48
#define XD 80              // DT_RANK + 2*D_STATE
#define MTOK (BB*LL)       // 2048 tokens

// ---------------- scratch (device globals; no allocation allowed) ----------------
__device__ __align__(128) float g_xz    [(size_t)BB*LL*2*DI];   // in_proj out, orig order
__device__ __align__(128) float g_xt    [(size_t)2*BB*LL*DI];   // conv+silu out, per-dir
__device__ __align__(128) float g_xdbl  [(size_t)2*BB*LL*XD];   // x_proj out (full fp32, for scan)
__device__ __align__(128) float g_xdbl_r[(size_t)2*BB*LL*XD];   // tf32-rounded copy (dt GEMM A)
__device__ __align__(128) float g_delta [(size_t)2*BB*LL*DI];   // softplus(dt proj)
__device__ __align__(128) float g_y     [(size_t)BB*LL*DI];     // y_f + y_r (atomic), orig order
__device__ __align__(128) float g_hs_r  [(size_t)MTOK*DM];      // tf32-rounded hidden_states
__device__ __align__(128) float g_wi_r  [(size_t)2*DI*DM];      // tf32-rounded in_proj_w
__device__ __align__(128) float g_wo_r  [(size_t)DM*DI];        // tf32-rounded out_proj_w
__device__ __align__(128) float g_wdt   [(size_t)2*DI*DTR];     // tf32-rounded dt_w (f,r)
__device__ __align__(128) float g_dtb   [(size_t)2*DI];         // dt bias (f,r), fp32

__device__ __forceinline__ float softplusf(float x) {
    return fmaxf(x, 0.f) + log1pf(expf(-fabsf(x)));
}
__device__ __forceinline__ float tf32r(float x) {
    unsigned u;
    asm("cvt.rna.tf32.f32 %0, %1;" : "=r"(u) : "f"(x));
    return __uint_as_float(u);
}

// ---------------- prep: tf32-round weights/inputs once; zero y accumulator ------
__global__ void prep_kernel(
    const float* __restrict__ hs, const float* __restrict__ wi,
    const float* __restrict__ wo,
    const float* __restrict__ dtwf, const float* __restrict__ dtwr,
    const float* __restrict__ dtbf, const float* __restrict__ dtbr,
    float* __restrict__ hs_r, float* __restrict__ wi_r, float* __restrict__ wo_r,
    float* __restrict__ wdt, float* __restrict__ dtb, float* __restrict__ yz)
{
    int tid = blockIdx.x * blockDim.x + threadIdx.x;
    int stride = gridDim.x * blockDim.x;
    for (int i = tid; i < MTOK * DM; i += stride)       hs_r[i] = tf32r(hs[i]);
    for (int i = tid; i < 2 * DI * DM; i += stride)     wi_r[i] = tf32r(wi[i]);
    for (int i = tid; i < DM * DI; i += stride)         wo_r[i] = tf32r(wo[i]);
    for (int i = tid; i < DI * DTR; i += stride) {
        wdt[i]            = tf32r(dtwf[i]);
        wdt[DI * DTR + i] = tf32r(dtwr[i]);
    }
    for (int i = tid; i < DI; i += stride) {
        dtb[i]      = dtbf[i];
        dtb[DI + i] = dtbr[i];
    }
    for (int i = tid; i < BB * LL * DI; i += stride)    yz[i] = 0.f;
}

// ---------------- tf32 tensor-core TN GEMM, cp.async 2-stage, cvt-free ----------
// C[m,n] = act(sum_k A[m,k]*W[n,k] + bias[n]). Operands pre-rounded to tf32.
// BM=BN=128, BK=16, 256 thr (8 warps 2x4, warp tile 64x32, m16n8k8).
// blockIdx.z selects a (A,W,bias,C) set via strides. M%128==N%128==K%16==0.
__global__ void __launch_bounds__(256, 2) tf32_gemm(
    const float* __restrict__ Ab, size_t Az,
    const float* __restrict__ Wb, size_t Wz,
    const float* __restrict__ biasb, size_t Bz,
    float* __restrict__ Cb, size_t Cz,
    int M, int N, int K, int lda, int act)
{
    const float* A = Ab + (size_t)blockIdx.z * Az;
    const float* W = Wb + (size_t)blockIdx.z * Wz;
    const float* bias = biasb ? biasb + (size_t)blockIdx.z * Bz : nullptr;
    float* C = Cb + (size_t)blockIdx.z * Cz;

    __shared__ float As[2][128][20];
    __shared__ float Ws[2][128][20];

    const int m0 = blockIdx.y * 128;
    const int n0 = blockIdx.x * 128;
    const int t    = threadIdx.x;
    const int lane = t & 31;
    const int wid  = t >> 5;
    const int wm   = wid & 1;        // M dim (64 rows each)
    const int wn   = wid >> 1;       // N dim (32 cols each)
    const int g    = lane >> 2;      // 0..7
    const int tg   = lane & 3;       // 0..3

    float acc[4][4][4];
    #pragma unroll
    for (int mt = 0; mt < 4; mt++)
        #pragma unroll
        for (int nt = 0; nt < 4; nt++)
            #pragma unroll
            for (int r = 0; r < 4; r++) acc[mt][nt][r] = 0.f;

    const int nIter = K / 16;

    auto load_stage = [&](int s, int k0) {
        #pragma unroll
        for (int it = 0; it < 2; it++) {
            int c = t + it * 256;
            int row = c >> 2;
            int kc  = (c & 3) << 2;
            unsigned da = (unsigned)__cvta_generic_to_shared(&As[s][row][kc]);
            const float* sa = A + (size_t)(m0 + row) * lda + k0 + kc;
            asm volatile("cp.async.cg.shared.global [%0], [%1], 16;\n"
                         :: "r"(da), "l"(sa));
            unsigned dw = (unsigned)__cvta_generic_to_shared(&Ws[s][row][kc]);
            const float* sw = W + (size_t)(n0 + row) * K + k0 + kc;
            asm volatile("cp.async.cg.shared.global [%0], [%1], 16;\n"
                         :: "r"(dw), "l"(sw));
        }
        asm volatile("cp.async.commit_group;\n" ::);
    };

    load_stage(0, 0);
    if (nIter > 1) load_stage(1, 16);

    for (int i = 0; i < nIter; i++) {
        int b = i & 1;
        if (i + 1 < nIter) asm volatile("cp.async.wait_group 1;\n" ::);
        else               asm volatile("cp.async.wait_group 0;\n" ::);
        __syncthreads();

        #pragma unroll
        for (int ks = 0; ks < 16; ks += 8) {
            unsigned a[4][4], bfr[4][2];
            #pragma unroll
            for (int mt = 0; mt < 4; mt++) {
                int mr = wm * 64 + mt * 16 + g;
                a[mt][0] = __float_as_uint(As[b][mr    ][ks + tg]);
                a[mt][1] = __float_as_uint(As[b][mr + 8][ks + tg]);
                a[mt][2] = __float_as_uint(As[b][mr    ][ks + tg + 4]);
                a[mt][3] = __float_as_uint(As[b][mr + 8][ks + tg + 4]);
            }
            #pragma unroll
            for (int nt = 0; nt < 4; nt++) {
                int nc = wn * 32 + nt * 8 + g;
                bfr[nt][0] = __float_as_uint(Ws[b][nc][ks + tg]);
                bfr[nt][1] = __float_as_uint(Ws[b][nc][ks + tg + 4]);
            }
            #pragma unroll
            for (int mt = 0; mt < 4; mt++)
                #pragma unroll
                for (int nt = 0; nt < 4; nt++) {
                    asm volatile(
                        "mma.sync.aligned.m16n8k8.row.col.f32.tf32.tf32.f32 "
                        "{%0,%1,%2,%3}, {%4,%5,%6,%7}, {%8,%9}, {%0,%1,%2,%3};"
                        : "+f"(acc[mt][nt][0]), "+f"(acc[mt][nt][1]),
                          "+f"(acc[mt][nt][2]), "+f"(acc[mt][nt][3])
                        : "r"(a[mt][0]), "r"(a[mt][1]), "r"(a[mt][2]), "r"(a[mt][3]),
                          "r"(bfr[nt][0]), "r"(bfr[nt][1]));
                }
        }
        __syncthreads();
        if (i + 2 < nIter) load_stage(b, (i + 2) * 16);
    }

    // epilogue: c0/c1 at (row g, cols 2tg,2tg+1); c2/c3 at row g+8
    #pragma unroll
    for (int mt = 0; mt < 4; mt++) {
        int r0 = m0 + wm * 64 + mt * 16 + g;
        #pragma unroll
        for (int nt = 0; nt < 4; nt++) {
            int c0 = n0 + wn * 32 + nt * 8 + 2 * tg;
            float v0 = acc[mt][nt][0], v1 = acc[mt][nt][1];
            float v2 = acc[mt][nt][2], v3 = acc[mt][nt][3];
            if (bias) {
                float b0 = bias[c0], b1 = bias[c0 + 1];
                v0 += b0; v1 += b1; v2 += b0; v3 += b1;
            }
            if (act == 1) {
                v0 = softplusf(v0); v1 = softplusf(v1);
                v2 = softplusf(v2); v3 = softplusf(v3);
            }
            *(float2*)(C + (size_t)r0 * N + c0)       = make_float2(v0, v1);
            *(float2*)(C + (size_t)(r0 + 8) * N + c0) = make_float2(v2, v3);
        }
    }
}

// ---------------- depthwise causal conv1d + silu, both directions ----------------
__global__ void conv_silu_kernel(
    const float* __restrict__ xz,
    const float* __restrict__ cwf, const float* __restrict__ cbf,
    const float* __restrict__ cwr, const float* __restrict__ cbr,
    float* __restrict__ xt)
{
    long idx = (long)blockIdx.x * blockDim.x + threadIdx.x;
    if (idx >= (long)2 * BB * LL * DI) return;
    int d   = (int)(idx % DI);
    int p   = (int)((idx / DI) % LL);
    int b   = (int)((idx / ((long)DI * LL)) % BB);
    int dir = (int)(idx / ((long)DI * LL * BB));

    const float* cw = dir ? cwr : cwf;
    const float* cb = dir ? cbr : cbf;
    float4 w4 = *(const float4*)(cw + d * 4);
    float wv[4] = {w4.x, w4.y, w4.z, w4.w};

    float acc = cb[d];
    const float* xbase = xz + (size_t)b * LL * 2 * DI + d;
    #pragma unroll
    for (int j = 0; j < 4; j++) {
        int q = p - 3 + j;
        if (q >= 0) {
            int ol = dir ? (LL - 1 - q) : q;
            acc = fmaf(wv[j], xbase[(size_t)ol * 2 * DI], acc);
        }
    }
    float s = acc / (1.f + __expf(-acc));   // silu
    xt[idx] = s;
}

// ---------------- skinny-N GEMM for x_proj: (2048 x 1536) @ (1536 x 80) per dir ----
// Writes full-precision xdbl (for scan) and tf32-rounded copy (for dt GEMM A).
__global__ void __launch_bounds__(256) xproj_gemm(
    const float* __restrict__ xt,
    const float* __restrict__ wf, const float* __restrict__ wr,
    float* __restrict__ xdbl, float* __restrict__ xdbl_r)
{
    int dir = blockIdx.y;
    const float* W = dir ? wr : wf;
    const float* A = xt     + (size_t)dir * BB * LL * DI;
    float*       C = xdbl   + (size_t)dir * BB * LL * XD;
    float*       Cr = xdbl_r + (size_t)dir * BB * LL * XD;
    int m0 = blockIdx.x * 16;

    __shared__ float As[32][16];
    __shared__ float Ws[32][XD];
    int t  = threadIdx.x;
    int m  = t >> 4;          // 0..15
    int nb = (t & 15) * 5;    // 0,5,...,75

    float acc[5] = {0.f, 0.f, 0.f, 0.f, 0.f};
    for (int k0 = 0; k0 < DI; k0 += 32) {
        #pragma unroll
        for (int it = 0; it < 2; it++) {
            int idx = t + it * 256;
            int row = idx >> 5, kk = idx & 31;
            As[kk][row] = A[(size_t)(m0 + row) * DI + k0 + kk];
        }
        #pragma unroll
        for (int it = 0; it < 10; it++) {
            int idx = t + it * 256;
            int row = idx >> 5, kk = idx & 31;
            Ws[kk][row] = W[(size_t)row * DI + k0 + kk];
        }
        __syncthreads();
        #pragma unroll
        for (int k = 0; k < 32; k++) {
            float a = As[k][m];
            #pragma unroll
            for (int j = 0; j < 5; j++)
                acc[j] = fmaf(a, Ws[k][nb + j], acc[j]);
        }
        __syncthreads();
    }
    #pragma unroll
    for (int j = 0; j < 5; j++) {
        size_t o = (size_t)(m0 + m) * XD + nb + j;
        C[o]  = acc[j];
        Cr[o] = tf32r(acc[j]);
    }
}

// ---------------- selective scan + D-skip + silu(z) gate; atomic y_f+y_r ----------
__global__ void __launch_bounds__(128) scan_kernel(
    const float* __restrict__ xz,   const float* __restrict__ xt,
    const float* __restrict__ xdbl, const float* __restrict__ delta,
    const float* __restrict__ Alog_f, const float* __restrict__ Df,
    const float* __restrict__ Alog_r, const float* __restrict__ Dr,
    float* __restrict__ y)
{
    int dir  = blockIdx.z, b = blockIdx.y;
    int warp = threadIdx.x >> 5, lane = threadIdx.x & 31;
    int half = (lane >> 4) & 1, n = lane & 15;
    int d = blockIdx.x * 8 + warp * 2 + half;

    const float* Alog = dir ? Alog_r : Alog_f;
    const float* Dp   = dir ? Dr     : Df;
    float Acoef = -expf(Alog[d * DS + n]);
    float Dd    = Dp[d];

    const float* pdl = delta + ((size_t)(dir * BB + b) * LL) * DI + d;
    const float* pu  = xt    + ((size_t)(dir * BB + b) * LL) * DI + d;
    const float* px  = xdbl  + ((size_t)(dir * BB + b) * LL) * XD;
    const float* pz  = xz    + (size_t)b * LL * 2 * DI + DI + d;
    float*       py  = y     + (size_t)b * LL * DI + d;

    float h = 0.f;
    #pragma unroll 4
    for (int t = 0; t < LL; t++) {
        float dt_ = pdl[(size_t)t * DI];
        float u   = pu [(size_t)t * DI];
        float Bv  = px[t * XD + DTR + n];
        float Cv  = px[t * XD + DTR + DS + n];
        float dA  = __expf(dt_ * Acoef);
        h = fmaf(dA, h, (dt_ * u) * Bv);
        float part = h * Cv;
        part += __shfl_down_sync(0xffffffffu, part, 8, 16);
        part += __shfl_down_sync(0xffffffffu, part, 4, 16);
        part += __shfl_down_sync(0xffffffffu, part, 2, 16);
        part += __shfl_down_sync(0xffffffffu, part, 1, 16);
        if (n == 0) {
            int ol = dir ? (LL - 1 - t) : t;
            float zv = pz[(size_t)ol * 2 * DI];
            float yv = part + Dd * u;
            float sg = zv / (1.f + __expf(-zv));   // silu(z)
            atomicAdd(&py[(size_t)ol * DI], tf32r(yv * sg));
        }
    }
}

// ---------------- launch ----------------
extern "C" void kernel_launch(void* const* d_in, const int* in_sizes, int n_in,
                              void* d_out, int out_size)
{
    const float* hs   = (const float*)d_in[0];
    const float* wi   = (const float*)d_in[1];
    const float* wo   = (const float*)d_in[2];
    const float* cwf  = (const float*)d_in[3];
    const float* cbf  = (const float*)d_in[4];
    const float* xpf  = (const float*)d_in[5];
    const float* dtwf = (const float*)d_in[6];
    const float* dtbf = (const float*)d_in[7];
    const float* alf  = (const float*)d_in[8];
    const float* Dfp  = (const float*)d_in[9];
    const float* cwr  = (const float*)d_in[10];
    const float* cbr  = (const float*)d_in[11];
    const float* xpr  = (const float*)d_in[12];
    const float* dtwr = (const float*)d_in[13];
    const float* dtbr = (const float*)d_in[14];
    const float* alr  = (const float*)d_in[15];
    const float* Drp  = (const float*)d_in[16];
    float* out = (float*)d_out;

    float *xz, *xt, *xdbl, *xdbl_r, *delta, *y, *hs_r, *wi_r, *wo_r, *wdt, *dtb;
    cudaGetSymbolAddress((void**)&xz,     g_xz);
    cudaGetSymbolAddress((void**)&xt,     g_xt);
    cudaGetSymbolAddress((void**)&xdbl,   g_xdbl);
    cudaGetSymbolAddress((void**)&xdbl_r, g_xdbl_r);
    cudaGetSymbolAddress((void**)&delta,  g_delta);
    cudaGetSymbolAddress((void**)&y,      g_y);
    cudaGetSymbolAddress((void**)&hs_r,   g_hs_r);
    cudaGetSymbolAddress((void**)&wi_r,   g_wi_r);
    cudaGetSymbolAddress((void**)&wo_r,   g_wo_r);
    cudaGetSymbolAddress((void**)&wdt,    g_wdt);
    cudaGetSymbolAddress((void**)&dtb,    g_dtb);

    const size_t dir_xd = (size_t)BB * LL * XD;
    const size_t dir_di = (size_t)BB * LL * DI;

    // 0. prep: tf32-round weights + hs, copy dt biases, zero y
    prep_kernel<<<2048, 256>>>(hs, wi, wo, dtwf, dtwr, dtbf, dtbr,
                               hs_r, wi_r, wo_r, wdt, dtb, y);

    // 1. shared in_proj: xz = hs @ wi^T  (2048 x 3072 x 768)
    tf32_gemm<<<dim3(2 * DI / 128, MTOK / 128, 1), 256>>>(
        hs_r, 0, wi_r, 0, nullptr, 0, xz, 0, MTOK, 2 * DI, DM, DM, 0);

    // 2. depthwise conv + silu, both dirs
    long total = (long)2 * BB * LL * DI;
    conv_silu_kernel<<<(unsigned)((total + 255) / 256), 256>>>(
        xz, cwf, cbf, cwr, cbr, xt);

    // 3. x_proj, both dirs (writes fp32 + tf32-rounded copies)
    xproj_gemm<<<dim3(MTOK / 16, 2), 256>>>(xt, xpf, xpr, xdbl, xdbl_r);

    // 4. dt projection + softplus, BOTH dirs in one launch (z = dir)
    tf32_gemm<<<dim3(DI / 128, MTOK / 128, 2), 256>>>(
        xdbl_r, dir_xd, wdt, (size_t)DI * DTR, dtb, (size_t)DI,
        delta, dir_di, MTOK, DI, DTR, XD, 1);

    // 5. selective scan + gate; atomically accumulates y_f + y_r into zeroed y
    scan_kernel<<<dim3(DI / 8, BB, 2), 128>>>(
        xz, xt, xdbl, delta, alf, Dfp, alr, Drp, y);

    // 6. shared out_proj on accumulated y  (2048 x 768 x 1536)
    tf32_gemm<<<dim3(DM / 128, MTOK / 128, 1), 256>>>(
        y, 0, wo_r, 0, nullptr, 0, out, 0, MTOK, DM, DI, DI, 0);
}